// round 12
// baseline (speedup 1.0000x reference)
#include <cuda_runtime.h>
#include <cuda_fp16.h>

#define B_ 2
#define L_ 24
#define C_ 16
#define H_ 64
#define W_ 64
#define HW_ 4096

// fp16 images, layout [b][l][cq(2)][HW][8ch] : 16 B per (pixel, channel-oct)
__device__ __half g_imgh[(size_t)B_ * L_ * 2 * HW_ * 8];

// ---------------------------------------------------------------------------
// Kernel 1: repack [B][L][C][HW] fp32 -> [b][l][cq][HW][8] fp16.
// ---------------------------------------------------------------------------
__global__ __launch_bounds__(256) void transpose_kernel(const float* __restrict__ images) {
    int idx = blockIdx.x * blockDim.x + threadIdx.x;   // over B*L*2*HW
    int p = idx & (HW_ - 1);
    int cq = (idx >> 12) & 1;
    int bl = idx >> 13;
    const float* src = images + ((size_t)bl * C_ + cq * 8) * HW_ + p;
    __half2 h[4];
#pragma unroll
    for (int j = 0; j < 4; ++j)
        h[j] = __floats2half2_rn(src[(2 * j) * HW_], src[(2 * j + 1) * HW_]);
    ((uint4*)g_imgh)[idx] = *(uint4*)h;
}

// ---------------------------------------------------------------------------
// Accumulate 8 fp16 channels (one uint4) * weight into fp32 acc.
// ---------------------------------------------------------------------------
__device__ __forceinline__ void accum8(float* acc, uint4 a, float w) {
    unsigned wds[4] = {a.x, a.y, a.z, a.w};
#pragma unroll
    for (int j = 0; j < 4; ++j) {
        float2 f = __half22float2(*(__half2*)&wds[j]);
        acc[2 * j]     = fmaf(w, f.x, acc[2 * j]);
        acc[2 * j + 1] = fmaf(w, f.y, acc[2 * j + 1]);
    }
}

// ---------------------------------------------------------------------------
// One bilinear sample of frame (imgu = cq0 plane ptr in uint4 units),
// accumulated into acc[16] with relative flow (relx, rely).
// ---------------------------------------------------------------------------
__device__ __forceinline__ void sample_frame(const uint4* __restrict__ imgu,
                                             float ax, float yf,
                                             float relx, float rely,
                                             float* acc) {
    // wrap x: u = (gx+1) mod 2, ix = u*32 - 0.5 in [-0.5, 63.5)
    float u0 = ax + relx;
    float u = u0 - 2.0f * floorf(0.5f * u0);
    float ixf = fmaf(u, 32.0f, -0.5f);
    float iyf = fmaf(rely, 32.0f, yf);

    float x0f = floorf(ixf), y0f = floorf(iyf);
    float wx1 = ixf - x0f, wy1 = iyf - y0f;
    float wx0 = 1.0f - wx1, wy0 = 1.0f - wy1;
    int x0 = (int)x0f, y0 = (int)y0f;

    // validity folded into weights (x wrapped => x0 in [-1,63])
    if (x0 < 0) wx0 = 0.0f;
    if (x0 > 62) wx1 = 0.0f;
    if ((unsigned)y0 > 63u) wy0 = 0.0f;
    if ((unsigned)(y0 + 1) > 63u) wy1 = 0.0f;

    float w00 = wx0 * wy0, w10 = wx1 * wy0;
    float w01 = wx0 * wy1, w11 = wx1 * wy1;

    int x0c = max(x0, 0), x1c = min(x0 + 1, 63);
    int y0c = min(max(y0, 0), 63), y1c = min(max(y0 + 1, 0), 63);
    int p00 = (y0c << 6) + x0c, p10 = (y0c << 6) + x1c;
    int p01 = (y1c << 6) + x0c, p11 = (y1c << 6) + x1c;

    const uint4* hi = imgu + HW_;
    // batch all 8 corner loads for MLP
    uint4 a00 = imgu[p00], a10 = imgu[p10], a01 = imgu[p01], a11 = imgu[p11];
    uint4 b00 = hi[p00],   b10 = hi[p10],   b01 = hi[p01],   b11 = hi[p11];

    accum8(acc,     a00, w00); accum8(acc,     a10, w10);
    accum8(acc,     a01, w01); accum8(acc,     a11, w11);
    accum8(acc + 8, b00, w00); accum8(acc + 8, b10, w10);
    accum8(acc + 8, b01, w01); accum8(acc + 8, b11, w11);
}

// ---------------------------------------------------------------------------
// Kernel 2: main gather, decoupled.
// Phase 1: per-thread flow prefix-sum -> rel(k) for all k in private smem
//          (no cross-thread sharing, no __syncthreads needed).
// Phase 2: k-loop with NO cross-iteration dependency (addresses from smem),
//          unroll 2 -> 16 gather loads in flight.
// Block = 128 threads = 2 rows; grid (32, 24, 2), t descending.
// ---------------------------------------------------------------------------
__global__ __launch_bounds__(128) void warp_kernel(const float* __restrict__ flows,
                                                   float* __restrict__ out) {
    __shared__ float2 srel[L_][128];   // 24 KB: rel(k) per thread

    int tid = threadIdx.x;
    int x = tid & 63;
    int y = (blockIdx.x << 1) + (tid >> 6);
    int t = (L_ - 1) - (int)blockIdx.y;
    int b = blockIdx.z;
    int p = (y << 6) + x;

    float ax = (float)(2 * x + 1) * (1.0f / 64.0f);  // (bx + 1), pre-wrap
    float yf = (float)y;                              // iy = rely*32 + y

    // ---- Phase 1: rel(k) = sum_{j=k+1..t} f_j, stored for each k ----
    const float* fbase = flows + ((size_t)(b * L_)) * 2 * HW_ + p;
    float rx = 0.0f, ry = 0.0f;
    srel[t][tid] = make_float2(0.0f, 0.0f);
#pragma unroll 4
    for (int j = t; j >= 1; --j) {
        rx += fbase[(size_t)j * 2 * HW_];
        ry += fbase[(size_t)j * 2 * HW_ + HW_];
        srel[j - 1][tid] = make_float2(rx, ry);
    }

    // ---- Phase 2: independent gather per k ----
    const uint4* imgu0 = (const uint4*)g_imgh + (size_t)(b * L_) * 2 * HW_;
    float acc[C_];
#pragma unroll
    for (int c = 0; c < C_; ++c) acc[c] = 0.0f;

#pragma unroll 2
    for (int k = 0; k <= t; ++k) {
        float2 r = srel[k][tid];
        sample_frame(imgu0 + (size_t)k * 2 * HW_, ax, yf, r.x, r.y, acc);
    }

    // out layout [B][L][C][H][W]; warp writes 128B coalesced per channel
    float* op = out + ((size_t)(b * L_ + t) * C_) * HW_ + p;
#pragma unroll
    for (int c = 0; c < C_; ++c) op[c * HW_] = acc[c];
}

extern "C" void kernel_launch(void* const* d_in, const int* in_sizes, int n_in,
                              void* d_out, int out_size) {
    const float* flows = (const float*)d_in[0];
    const float* images = (const float*)d_in[1];
    float* out = (float*)d_out;

    transpose_kernel<<<(B_ * L_ * 2 * HW_) / 256, 256>>>(images);
    dim3 grid(32, L_, B_);
    warp_kernel<<<grid, 128>>>(flows, out);
}

// round 13
// speedup vs baseline: 1.4956x; 1.4956x over previous
#include <cuda_runtime.h>
#include <cuda_fp16.h>

#define B_ 2
#define L_ 24
#define C_ 16
#define H_ 64
#define W_ 64
#define HW_ 4096

// fp16 images, layout [b][l][cq(2)][HW][8ch] : 16 B per (pixel, channel-oct)
__device__ __half g_imgh[(size_t)B_ * L_ * 2 * HW_ * 8];

// ---------------------------------------------------------------------------
// Kernel 1: repack [B][L][C][HW] fp32 -> [b][l][cq][HW][8] fp16.
// ---------------------------------------------------------------------------
__global__ __launch_bounds__(256) void transpose_kernel(const float* __restrict__ images) {
    int idx = blockIdx.x * blockDim.x + threadIdx.x;   // over B*L*2*HW
    int p = idx & (HW_ - 1);
    int cq = (idx >> 12) & 1;
    int bl = idx >> 13;
    const float* src = images + ((size_t)bl * C_ + cq * 8) * HW_ + p;
    __half2 h[4];
#pragma unroll
    for (int j = 0; j < 4; ++j)
        h[j] = __floats2half2_rn(src[(2 * j) * HW_], src[(2 * j + 1) * HW_]);
    ((uint4*)g_imgh)[idx] = *(uint4*)h;
}

// ---------------------------------------------------------------------------
// Accumulate 8 fp16 channels (one uint4) * weight into fp32 acc.
// ---------------------------------------------------------------------------
__device__ __forceinline__ void accum8(float* acc, uint4 a, float w) {
    unsigned wds[4] = {a.x, a.y, a.z, a.w};
#pragma unroll
    for (int j = 0; j < 4; ++j) {
        float2 f = __half22float2(*(__half2*)&wds[j]);
        acc[2 * j]     = fmaf(w, f.x, acc[2 * j]);
        acc[2 * j + 1] = fmaf(w, f.y, acc[2 * j + 1]);
    }
}

// ---------------------------------------------------------------------------
// One bilinear sample of frame (imgu = cq0 plane ptr in uint4 units),
// accumulated into acc[16] with relative flow (relx, rely).
// ---------------------------------------------------------------------------
__device__ __forceinline__ void sample_frame(const uint4* __restrict__ imgu,
                                             float ax, float yf,
                                             float relx, float rely,
                                             float* acc) {
    // wrap x: u = (gx+1) mod 2, ix = u*32 - 0.5 in [-0.5, 63.5)
    float u0 = ax + relx;
    float u = u0 - 2.0f * floorf(0.5f * u0);
    float ixf = fmaf(u, 32.0f, -0.5f);
    float iyf = fmaf(rely, 32.0f, yf);

    float x0f = floorf(ixf), y0f = floorf(iyf);
    float wx1 = ixf - x0f, wy1 = iyf - y0f;
    float wx0 = 1.0f - wx1, wy0 = 1.0f - wy1;
    int x0 = (int)x0f, y0 = (int)y0f;

    // validity folded into weights (x wrapped => x0 in [-1,63])
    if (x0 < 0) wx0 = 0.0f;
    if (x0 > 62) wx1 = 0.0f;
    if ((unsigned)y0 > 63u) wy0 = 0.0f;
    if ((unsigned)(y0 + 1) > 63u) wy1 = 0.0f;

    float w00 = wx0 * wy0, w10 = wx1 * wy0;
    float w01 = wx0 * wy1, w11 = wx1 * wy1;

    int x0c = max(x0, 0), x1c = min(x0 + 1, 63);
    int y0c = min(max(y0, 0), 63), y1c = min(max(y0 + 1, 0), 63);
    int p00 = (y0c << 6) + x0c, p10 = (y0c << 6) + x1c;
    int p01 = (y1c << 6) + x0c, p11 = (y1c << 6) + x1c;

    const uint4* hi = imgu + HW_;
    // batch all 8 corner loads for MLP
    uint4 a00 = imgu[p00], a10 = imgu[p10], a01 = imgu[p01], a11 = imgu[p11];
    uint4 b00 = hi[p00],   b10 = hi[p10],   b01 = hi[p01],   b11 = hi[p11];

    accum8(acc,     a00, w00); accum8(acc,     a10, w10);
    accum8(acc,     a01, w01); accum8(acc,     a11, w11);
    accum8(acc + 8, b00, w00); accum8(acc + 8, b10, w10);
    accum8(acc + 8, b01, w01); accum8(acc + 8, b11, w11);
}

// ---------------------------------------------------------------------------
// Kernel 2: main gather. 1 lane = 1 pixel, all 16 channels.
// Block = 128 threads = 2 rows of one (b,t); grid (32, 24, 2), t descending.
// rel flow recurrence with a 2-deep register double-buffer: the flow value
// consumed at iteration k was loaded two iterations earlier, so the L2-hit
// latency is off the rel-update critical chain.
// ---------------------------------------------------------------------------
__global__ __launch_bounds__(128) void warp_kernel(const float* __restrict__ flows,
                                                   float* __restrict__ out) {
    int tid = threadIdx.x;
    int x = tid & 63;
    int y = (blockIdx.x << 1) + (tid >> 6);
    int t = (L_ - 1) - (int)blockIdx.y;
    int b = blockIdx.z;
    int p = (y << 6) + x;

    float ax = (float)(2 * x + 1) * (1.0f / 64.0f);  // (bx + 1), pre-wrap
    float yf = (float)y;                              // iy = rely*32 + y

    const float* f = flows + ((size_t)(b * L_)) * 2 * HW_ + p;  // f[j]: frame j flow
    const uint4* imgu = (const uint4*)g_imgh + (size_t)(b * L_ + t) * 2 * HW_;

    // 2-deep flow prefetch: cur = flow[t], nxt = flow[t-1]
    float cx = 0.0f, cy = 0.0f, nx = 0.0f, ny = 0.0f;
    if (t >= 1) { cx = f[(size_t)t * 2 * HW_]; cy = f[(size_t)t * 2 * HW_ + HW_]; }
    if (t >= 2) { nx = f[(size_t)(t - 1) * 2 * HW_]; ny = f[(size_t)(t - 1) * 2 * HW_ + HW_]; }

    float relx = 0.0f, rely = 0.0f;
    float acc[C_];
#pragma unroll
    for (int c = 0; c < C_; ++c) acc[c] = 0.0f;

    for (int k = t; k > 0; --k) {
        sample_frame(imgu, ax, yf, relx, rely, acc);
        relx += cx;                    // flow[k], loaded >= 2 iters ago
        rely += cy;
        cx = nx; cy = ny;
        if (k >= 3) {                  // issue load of flow[k-2] now
            nx = f[(size_t)(k - 2) * 2 * HW_];
            ny = f[(size_t)(k - 2) * 2 * HW_ + HW_];
        }
        imgu -= 2 * HW_;
    }
    // k = 0: no flow update
    sample_frame(imgu, ax, yf, relx, rely, acc);

    // out layout [B][L][C][H][W]; warp writes 128B coalesced per channel
    float* op = out + ((size_t)(b * L_ + t) * C_) * HW_ + p;
#pragma unroll
    for (int c = 0; c < C_; ++c) op[c * HW_] = acc[c];
}

extern "C" void kernel_launch(void* const* d_in, const int* in_sizes, int n_in,
                              void* d_out, int out_size) {
    const float* flows = (const float*)d_in[0];
    const float* images = (const float*)d_in[1];
    float* out = (float*)d_out;

    transpose_kernel<<<(B_ * L_ * 2 * HW_) / 256, 256>>>(images);
    dim3 grid(32, L_, B_);
    warp_kernel<<<grid, 128>>>(flows, out);
}